// round 11
// baseline (speedup 1.0000x reference)
#include <cuda_runtime.h>
#include <cuda_bf16.h>

// out[b,i,j] = softmax_j( exp( exp(-||x_bi - x_bj||^2 * p) ) ), B=128, K=1024.
//
// R11 = R10 + hybrid outer exp. Completing the pipe model shows MUFU (not
// shown by ncu_to_text) was the top pipe: 2 EX2/elem = 8.4M warp-instrs / 74
// per-cyc = ~64us. Move the OUTER exp of 2 of 4 columns to an FMA polynomial
// (e^A = Taylor4(A/4)^4 on A in (0,1], rel err <= 4e-5, validated in R2):
//   MUFU 64 -> 48us, FMA 39 -> 56us  => max pipe 64 -> 56us.
//  - Poly columns need A = exp(-d*p) itself, so the log2(log2e) bias is
//    removed from cw.z/cw.w once per thread (2 FADD).
//  - Everything else identical to R10: SoA prep kernel, coalesced LDG.128,
//    8 rows / 4 cols per lane, deferred butterfly, STG.128.CS.

static constexpr int K = 1024;
static constexpr int B = 128;
static constexpr int BK = B * K;          // 131072 points
static constexpr int THREADS = 256;
static constexpr int ROWS = 8;
static constexpr float LOG2E = 1.4426950408889634f;
static constexpr float LOG2_LOG2E = 0.5287663729448977f;  // log2(log2(e))

// 8 x 512KB = 4MB scratch (static device arrays; no dynamic alloc).
__device__ __align__(16) float g_cx[BK];
__device__ __align__(16) float g_cy[BK];
__device__ __align__(16) float g_cz[BK];
__device__ __align__(16) float g_cw[BK];
__device__ __align__(16) float g_rx[BK];
__device__ __align__(16) float g_ry[BK];
__device__ __align__(16) float g_rz[BK];
__device__ __align__(16) float g_rw[BK];

__device__ __forceinline__ float ex2f(float x) {
    float r;
    asm("ex2.approx.f32 %0, %1;" : "=f"(r) : "f"(x));
    return r;
}

// e^A for A in (0,1]: (Taylor4 of e^(A/4))^4.  4 FMA + 2 MUL, rel err <= ~4e-5.
__device__ __forceinline__ float exp_poly01(float A) {
    float p = fmaf(A, 1.6276042e-4f, 2.6041667e-3f);   // 1/6144, 1/384
    p = fmaf(p, A, 0.03125f);                          // 1/32
    p = fmaf(p, A, 0.25f);
    p = fmaf(p, A, 1.0f);
    p = p * p;
    return p * p;
}

__global__ void __launch_bounds__(256)
prep_kernel(const float* __restrict__ coords, const float* __restrict__ prec)
{
    const int i = blockIdx.x * 256 + threadIdx.x;   // point index < BK
    const float q  = -prec[0] * LOG2E;
    const float s2 = -2.0f * q;

    const float x = coords[i * 3 + 0];
    const float y = coords[i * 3 + 1];
    const float z = coords[i * 3 + 2];
    const float nq = fmaf(x, x, fmaf(y, y, z * z)) * q;

    g_rx[i] = x;       g_ry[i] = y;       g_rz[i] = z;       g_rw[i] = nq;
    g_cx[i] = x * s2;  g_cy[i] = y * s2;  g_cz[i] = z * s2;  g_cw[i] = nq + LOG2_LOG2E;
}

__global__ void __launch_bounds__(THREADS, 4)
adjacency_softmax_kernel(float* __restrict__ out)
{
    __shared__ float wsum[ROWS][9];    // per-warp row sums (padded)
    __shared__ float inv_s[ROWS];

    const int bq   = blockIdx.x >> 7;
    const int row0 = (blockIdx.x & 127) << 3;
    const int tid  = threadIdx.x;
    const int wid  = tid >> 5;
    const int lane = tid & 31;
    const int base = bq << 10;
    const int jb   = base + (wid << 7) + (lane << 2);   // 4 consecutive columns

    // ---- Column values: perfectly coalesced LDG.128 (4 wf each) ----
    const float4 cx = *reinterpret_cast<const float4*>(g_cx + jb);
    const float4 cy = *reinterpret_cast<const float4*>(g_cy + jb);
    const float4 cz = *reinterpret_cast<const float4*>(g_cz + jb);
    float4 cw = *reinterpret_cast<const float4*>(g_cw + jb);
    // cols 2,3 use the FMA-poly outer exp: their EX2 arg must give A itself.
    cw.z -= LOG2_LOG2E;
    cw.w -= LOG2_LOG2E;

    float v0[ROWS], v1[ROWS], v2[ROWS], v3[ROWS];

    #pragma unroll
    for (int rc = 0; rc < ROWS / 4; rc++) {
        // Row values for 4 rows: uniform LDG.128 (1 wf each after first touch).
        const int rb = base + row0 + rc * 4;
        float rx[4], ry[4], rz[4], rw[4];
        *reinterpret_cast<float4*>(rx) = *reinterpret_cast<const float4*>(g_rx + rb);
        *reinterpret_cast<float4*>(ry) = *reinterpret_cast<const float4*>(g_ry + rb);
        *reinterpret_cast<float4*>(rz) = *reinterpret_cast<const float4*>(g_rz + rb);
        *reinterpret_cast<float4*>(rw) = *reinterpret_cast<const float4*>(g_rw + rb);

        #pragma unroll
        for (int r = 0; r < 4; r++) {
            const int vr = rc * 4 + r;
            const float ax = rx[r], ay = ry[r], az = rz[r], aw = rw[r];

            float t0 = aw + cw.x;
            float t1 = aw + cw.y;
            float t2 = aw + cw.z;
            float t3 = aw + cw.w;
            t0 = fmaf(ax, cx.x, t0);
            t1 = fmaf(ax, cx.y, t1);
            t2 = fmaf(ax, cx.z, t2);
            t3 = fmaf(ax, cx.w, t3);
            t0 = fmaf(ay, cy.x, t0);
            t1 = fmaf(ay, cy.y, t1);
            t2 = fmaf(ay, cy.z, t2);
            t3 = fmaf(ay, cy.w, t3);
            t0 = fmaf(az, cz.x, t0);
            t1 = fmaf(az, cz.y, t1);
            t2 = fmaf(az, cz.z, t2);
            t3 = fmaf(az, cz.w, t3);

            // cols 0,1: outer exp on MUFU. cols 2,3: outer exp on FMA pipe.
            v0[vr] = ex2f(ex2f(t0));             // exp(exp(-d*p))
            v1[vr] = ex2f(ex2f(t1));
            v2[vr] = exp_poly01(ex2f(t2));
            v3[vr] = exp_poly01(ex2f(t3));
        }
    }

    // ---- Deferred cross-lane reduction: array-halving butterfly ----
    float s[ROWS];
    #pragma unroll
    for (int r = 0; r < ROWS; r++)
        s[r] = (v0[r] + v1[r]) + (v2[r] + v3[r]);

    #pragma unroll
    for (int stage = 0; stage < 3; stage++) {
        const int m = 1 << stage;        // xor mask: 1, 2, 4
        const int h = 4 >> stage;        // surviving half-size: 4, 2, 1
        const bool up = (lane & m) != 0;
        #pragma unroll
        for (int r = 0; r < h; r++) {
            const float x = up ? s[r + h] : s[r];
            const float y = up ? s[r]     : s[r + h];
            s[r] = x + __shfl_xor_sync(0xFFFFFFFFu, y, m);
        }
    }
    {
        float t = s[0];
        t += __shfl_xor_sync(0xFFFFFFFFu, t, 8);
        t += __shfl_xor_sync(0xFFFFFFFFu, t, 16);
        if (lane < 8) {
            const int row = ((lane & 1) << 2) | (lane & 2) | ((lane & 4) >> 2);
            wsum[row][wid] = t;
        }
    }
    __syncthreads();

    if (tid < ROWS) {
        float acc = 0.0f;
        #pragma unroll
        for (int w = 0; w < 8; w++) acc += wsum[tid][w];
        inv_s[tid] = __fdividef(1.0f, acc);
    }
    __syncthreads();

    float* __restrict__ ob =
        out + ((size_t)bq * K + row0) * K + (jb - base);

    #pragma unroll
    for (int r = 0; r < ROWS; r++) {
        const float inv = inv_s[r];
        const float4 res = make_float4(v0[r] * inv, v1[r] * inv,
                                       v2[r] * inv, v3[r] * inv);
        __stcs(reinterpret_cast<float4*>(ob + (size_t)r * K), res);  // STG.128.CS
    }
}

extern "C" void kernel_launch(void* const* d_in, const int* in_sizes, int n_in,
                              void* d_out, int out_size)
{
    const float* coords = (const float*)d_in[0];   // [128, 1024, 3] f32
    const float* prec   = (const float*)d_in[1];   // [1] f32
    float* out          = (float*)d_out;           // [128, 1024, 1024] f32

    prep_kernel<<<BK / 256, 256>>>(coords, prec);
    dim3 grid(B * (K / ROWS));   // 16384 blocks
    adjacency_softmax_kernel<<<grid, THREADS>>>(out);
}